// round 7
// baseline (speedup 1.0000x reference)
#include <cuda_runtime.h>
#include <cstdint>

// ---------------------------------------------------------------------------
// Problem constants
// ---------------------------------------------------------------------------
#define NB    4096      // batch
#define DIN   2048
#define HH    1024
#define DD    256       // latent dim == HW
#define NSTEP 15
#define S     16        // samples per trace CTA

// ---------------------------------------------------------------------------
// Scratch (device globals; no allocation allowed)
// ---------------------------------------------------------------------------
__device__ float g_H   [2 * NB * HH];
__device__ float g_Z   [2 * NB * DD];   // z_s rows 0..4095, z_e rows 4096..8191
__device__ float g_HW  [NB * DD];
__device__ float g_V   [NB * DD];
__device__ float g_WpT [DD * DD];
__device__ float g_mind[NB];

// ---------------------------------------------------------------------------
// Packed fp32x2 helpers (FFMA2 — only reachable via PTX)
// ---------------------------------------------------------------------------
__device__ __forceinline__ unsigned long long pack2(float x, float y) {
    unsigned long long r;
    asm("mov.b64 %0, {%1, %2};" : "=l"(r) : "f"(x), "f"(y));
    return r;
}
__device__ __forceinline__ float2 unpack2(unsigned long long v) {
    float2 r;
    asm("mov.b64 {%0, %1}, %2;" : "=f"(r.x), "=f"(r.y) : "l"(v));
    return r;
}
__device__ __forceinline__ unsigned long long fma2(unsigned long long a,
                                                   unsigned long long b,
                                                   unsigned long long c) {
    unsigned long long d;
    asm("fma.rn.f32x2 %0, %1, %2, %3;" : "=l"(d) : "l"(a), "l"(b), "l"(c));
    return d;
}

// ---------------------------------------------------------------------------
// SGEMM (BM=128): C[z][M,N] = act(A_z[M,K] @ B[K,N] + bias[N]), row-major.
// ---------------------------------------------------------------------------
#define ASTRIDE 132

template <int ACT>
__global__ __launch_bounds__(256)
void sgemm_kernel(const float* __restrict__ A0, const float* __restrict__ A1,
                  const float* __restrict__ Bm,
                  const float* __restrict__ bias, float* __restrict__ C,
                  int M, int N, int K) {
    __shared__ __align__(16) float As[2 * 16 * ASTRIDE];
    __shared__ __align__(16) float Bs[2 * 16 * 128];

    const float* A = blockIdx.z ? A1 : A0;
    float* Cz = C + (size_t)blockIdx.z * M * N;

    const int tid  = threadIdx.x;
    const int brow = blockIdx.y * 128;
    const int bcol = blockIdx.x * 128;
    const int ty   = tid >> 4;
    const int tx   = tid & 15;

    const int arow = tid >> 1;
    const int acol = (tid & 1) * 8;
    const int br0  = tid >> 5;
    const int bcl  = (tid & 31) * 4;

    const float* Aptr = A  + (size_t)(brow + arow) * K + acol;
    const float* Bptr = Bm + (size_t)br0 * N + bcol + bcl;

    unsigned long long c2[8][4];
#pragma unroll
    for (int m = 0; m < 8; m++)
#pragma unroll
        for (int j = 0; j < 4; j++) c2[m][j] = 0ull;

    float4 a_rg0, a_rg1, b_rg0, b_rg1;

    a_rg0 = *(const float4*)(Aptr + 0);
    a_rg1 = *(const float4*)(Aptr + 4);
    b_rg0 = *(const float4*)(Bptr);
    b_rg1 = *(const float4*)(Bptr + (size_t)8 * N);
    {
        float am[8] = {a_rg0.x, a_rg0.y, a_rg0.z, a_rg0.w,
                       a_rg1.x, a_rg1.y, a_rg1.z, a_rg1.w};
#pragma unroll
        for (int c = 0; c < 8; c++) As[(acol + c) * ASTRIDE + arow] = am[c];
        *(float4*)&Bs[br0 * 128 + bcl]       = b_rg0;
        *(float4*)&Bs[(br0 + 8) * 128 + bcl] = b_rg1;
    }
    __syncthreads();

    int buf = 0;
    const int nblk = K / 16;
    for (int kb = 0; kb < nblk; kb++) {
        const bool has_next = (kb + 1 < nblk);
        if (has_next) {
            const int k0 = (kb + 1) * 16;
            a_rg0 = *(const float4*)(Aptr + k0);
            a_rg1 = *(const float4*)(Aptr + k0 + 4);
            b_rg0 = *(const float4*)(Bptr + (size_t)k0 * N);
            b_rg1 = *(const float4*)(Bptr + (size_t)(k0 + 8) * N);
        }

        const float* Asb = As + buf * 16 * ASTRIDE;
        const float* Bsb = Bs + buf * 16 * 128;
#pragma unroll
        for (int kk = 0; kk < 16; kk++) {
            float4 a0 = *(const float4*)&Asb[kk * ASTRIDE + ty * 8];
            float4 a1 = *(const float4*)&Asb[kk * ASTRIDE + ty * 8 + 4];
            const unsigned long long* brow2 =
                (const unsigned long long*)&Bsb[kk * 128 + tx * 8];
            unsigned long long b2[4];
#pragma unroll
            for (int j = 0; j < 4; j++) b2[j] = brow2[j];
            float am[8] = {a0.x, a0.y, a0.z, a0.w, a1.x, a1.y, a1.z, a1.w};
#pragma unroll
            for (int m = 0; m < 8; m++) {
                unsigned long long aa = pack2(am[m], am[m]);
#pragma unroll
                for (int j = 0; j < 4; j++) c2[m][j] = fma2(aa, b2[j], c2[m][j]);
            }
        }

        if (has_next) {
            float* Asn = As + (buf ^ 1) * 16 * ASTRIDE;
            float* Bsn = Bs + (buf ^ 1) * 16 * 128;
            float am[8] = {a_rg0.x, a_rg0.y, a_rg0.z, a_rg0.w,
                           a_rg1.x, a_rg1.y, a_rg1.z, a_rg1.w};
#pragma unroll
            for (int c = 0; c < 8; c++) Asn[(acol + c) * ASTRIDE + arow] = am[c];
            *(float4*)&Bsn[br0 * 128 + bcl]       = b_rg0;
            *(float4*)&Bsn[(br0 + 8) * 128 + bcl] = b_rg1;
            __syncthreads();
            buf ^= 1;
        }
    }

#pragma unroll
    for (int m = 0; m < 8; m++) {
        const int row = brow + ty * 8 + m;
        float* crow = Cz + (size_t)row * N + bcol + tx * 8;
#pragma unroll
        for (int j = 0; j < 4; j++) {
            float2 p = unpack2(c2[m][j]);
            const int n = bcol + tx * 8 + 2 * j;
            p.x += bias[n];
            p.y += bias[n + 1];
            if (ACT) { p.x = tanhf(p.x); p.y = tanhf(p.y); }
            *(float2*)&crow[2 * j] = p;
        }
    }
}

// ---------------------------------------------------------------------------
// SGEMM (BM=64): small-N GEMMs (N=256) — larger grids fill the chip.
// ---------------------------------------------------------------------------
#define AS64 68

template <int ACT>
__global__ __launch_bounds__(256)
void sgemm64_kernel(const float* __restrict__ A, const float* __restrict__ Bm,
                    const float* __restrict__ bias, float* __restrict__ C,
                    int M, int N, int K) {
    __shared__ __align__(16) float As[2 * 16 * AS64];
    __shared__ __align__(16) float Bs[2 * 16 * 128];

    const int tid  = threadIdx.x;
    const int brow = blockIdx.y * 64;
    const int bcol = blockIdx.x * 128;
    const int ty   = tid >> 4;
    const int tx   = tid & 15;

    const int arow = tid >> 2;
    const int acol = (tid & 3) * 4;
    const int br0  = tid >> 5;
    const int bcl  = (tid & 31) * 4;

    const float* Aptr = A  + (size_t)(brow + arow) * K + acol;
    const float* Bptr = Bm + (size_t)br0 * N + bcol + bcl;

    unsigned long long c2[4][4];
#pragma unroll
    for (int m = 0; m < 4; m++)
#pragma unroll
        for (int j = 0; j < 4; j++) c2[m][j] = 0ull;

    float4 a_rg, b_rg0, b_rg1;

    a_rg  = *(const float4*)(Aptr);
    b_rg0 = *(const float4*)(Bptr);
    b_rg1 = *(const float4*)(Bptr + (size_t)8 * N);
    {
        float am[4] = {a_rg.x, a_rg.y, a_rg.z, a_rg.w};
#pragma unroll
        for (int c = 0; c < 4; c++) As[(acol + c) * AS64 + arow] = am[c];
        *(float4*)&Bs[br0 * 128 + bcl]       = b_rg0;
        *(float4*)&Bs[(br0 + 8) * 128 + bcl] = b_rg1;
    }
    __syncthreads();

    int buf = 0;
    const int nblk = K / 16;
    for (int kb = 0; kb < nblk; kb++) {
        const bool has_next = (kb + 1 < nblk);
        if (has_next) {
            const int k0 = (kb + 1) * 16;
            a_rg  = *(const float4*)(Aptr + k0);
            b_rg0 = *(const float4*)(Bptr + (size_t)k0 * N);
            b_rg1 = *(const float4*)(Bptr + (size_t)(k0 + 8) * N);
        }

        const float* Asb = As + buf * 16 * AS64;
        const float* Bsb = Bs + buf * 16 * 128;
#pragma unroll
        for (int kk = 0; kk < 16; kk++) {
            float4 a0 = *(const float4*)&Asb[kk * AS64 + ty * 4];
            const unsigned long long* brow2 =
                (const unsigned long long*)&Bsb[kk * 128 + tx * 8];
            unsigned long long b2[4];
#pragma unroll
            for (int j = 0; j < 4; j++) b2[j] = brow2[j];
            float am[4] = {a0.x, a0.y, a0.z, a0.w};
#pragma unroll
            for (int m = 0; m < 4; m++) {
                unsigned long long aa = pack2(am[m], am[m]);
#pragma unroll
                for (int j = 0; j < 4; j++) c2[m][j] = fma2(aa, b2[j], c2[m][j]);
            }
        }

        if (has_next) {
            float* Asn = As + (buf ^ 1) * 16 * AS64;
            float* Bsn = Bs + (buf ^ 1) * 16 * 128;
            float am[4] = {a_rg.x, a_rg.y, a_rg.z, a_rg.w};
#pragma unroll
            for (int c = 0; c < 4; c++) Asn[(acol + c) * AS64 + arow] = am[c];
            *(float4*)&Bsn[br0 * 128 + bcl]       = b_rg0;
            *(float4*)&Bsn[(br0 + 8) * 128 + bcl] = b_rg1;
            __syncthreads();
            buf ^= 1;
        }
    }

#pragma unroll
    for (int m = 0; m < 4; m++) {
        const int row = brow + ty * 4 + m;
        float* crow = C + (size_t)row * N + bcol + tx * 8;
#pragma unroll
        for (int j = 0; j < 4; j++) {
            float2 p = unpack2(c2[m][j]);
            const int n = bcol + tx * 8 + 2 * j;
            p.x += bias[n];
            p.y += bias[n + 1];
            if (ACT) { p.x = tanhf(p.x); p.y = tanhf(p.y); }
            *(float2*)&crow[2 * j] = p;
        }
    }
}

// ---------------------------------------------------------------------------
// Wp1 transpose (tiny: 256x256)
// ---------------------------------------------------------------------------
__global__ void transpose256(const float* __restrict__ in, float* __restrict__ out) {
    int i = blockIdx.x, j = threadIdx.x;
    out[j * DD + i] = in[i * DD + j];
}

// ---------------------------------------------------------------------------
// Degenerate-wind fallback
// ---------------------------------------------------------------------------
__global__ void fallback_kernel(float* __restrict__ V, const float* __restrict__ noise) {
    __shared__ float rw[8], rn[8];
    const int s = blockIdx.x, t = threadIdx.x;
    const int lane = t & 31, warp = t >> 5;
    float w = V[s * DD + t];
    float n = noise[s * DD + t];
    float pw = w * w, pn = n * n;
#pragma unroll
    for (int off = 16; off > 0; off >>= 1) {
        pw += __shfl_xor_sync(0xffffffffu, pw, off);
        pn += __shfl_xor_sync(0xffffffffu, pn, off);
    }
    if (lane == 0) { rw[warp] = pw; rn[warp] = pn; }
    __syncthreads();
    float sw = 0.f, sn = 0.f;
#pragma unroll
    for (int i = 0; i < 8; i++) { sw += rw[i]; sn += rn[i]; }
    float wn = sqrtf(sw + 1e-24f);
    if (wn < 1e-5f) {
        float nn = sqrtf(sn + 1e-24f);
        V[s * DD + t] = w + n / (nn + 1e-12f) * 1e-4f;
    }
}

// ---------------------------------------------------------------------------
// Trace kernel v3: 16 samples per CTA, 256 threads (thread = dim index).
// Weight columns in 16-row compute blocks with one-block register lookahead:
// 128 FFMA2 (~256 fma cycles) per block >= L2 latency (~250cy) -> fully hidden.
// xacc/vacc live in per-thread-private smem columns (no barriers needed).
// Dynamic smem (floats): xt[4096]|sv[4096]|xa[4096]|va[4096]
//                        |red_a[128]|red_b[128]|bc_a[16]|bc_b[16]
// ---------------------------------------------------------------------------
#define TR_SMEM_FLOATS (4 * 4096 + 128 + 128 + 16 + 16)
#define TR_SMEM_BYTES  (TR_SMEM_FLOATS * 4)

__global__ __launch_bounds__(256)
void trace_kernel(const float* __restrict__ Z,    // [8192,256]: z_s | z_e
                  const float* __restrict__ V,    // [4096,256]
                  const float* __restrict__ Wp1,  // [256,256]
                  const float* __restrict__ WpT,  // transposed
                  const float* __restrict__ bp1,
                  const float* __restrict__ wp2,
                  float* __restrict__ mind) {
    extern __shared__ __align__(16) float dsm[];
    float* xt_sm = dsm;            // [i*S + s]
    float* sv_sm = dsm + 4096;     // [i*S + s]
    float* xa_sm = dsm + 8192;     // [s*DD + t]  (private per thread)
    float* va_sm = dsm + 12288;    // [s*DD + t]  (private per thread)
    float* red_a = dsm + 16384;
    float* red_b = dsm + 16512;
    float* bc_a  = dsm + 16640;
    float* bc_b  = dsm + 16656;

    const int t    = threadIdx.x;
    const int lane = t & 31;
    const int warp = t >> 5;
    const int s0   = blockIdx.x * S;
    const float hstep = 1.0f / 15.0f;
    const float bp = bp1[t];
    const float w2 = wp2[t];

    float x[S], v[S], vt[S], g[S];
#pragma unroll
    for (int s = 0; s < S; s++) {
        x[s] = Z[(size_t)(s0 + s) * DD + t];
        v[s] = V[(size_t)(s0 + s) * DD + t];
    }
    float mymin = 3.4e38f;

    // 8-row FMA sub-block (SRCP captured from MATVEC scope)
#define COMP8(WREG, WOFF, BASE, ACC2)                                          \
    _Pragma("unroll") for (int u = 0; u < 8; u++) {                            \
        unsigned long long wp = pack2(WREG[WOFF + u], WREG[WOFF + u]);         \
        const ulonglong2* xr = (const ulonglong2*)(SRCP + ((BASE) + u) * S);   \
        _Pragma("unroll") for (int k = 0; k < S / 4; k++) {                    \
            ulonglong2 xv = xr[k];                                             \
            ACC2[2 * k]     = fma2(wp, xv.x, ACC2[2 * k]);                     \
            ACC2[2 * k + 1] = fma2(wp, xv.y, ACC2[2 * k + 1]);                 \
        }                                                                      \
    }

    // matvec over 16-row blocks; next block's 16 weights prefetched during
    // the current block's 128 FFMA2 (~256 cycles of cover).
#define MATVEC(WBASE, SRC, ACC2)                                               \
    do {                                                                       \
        const float* Wcol = (WBASE) + t;                                       \
        const float* SRCP = (SRC);                                             \
        float wc[16], wn[16];                                                  \
        _Pragma("unroll") for (int u = 0; u < 16; u++) wc[u] = Wcol[u * DD];   \
        _Pragma("unroll") for (int k = 0; k < S / 2; k++) ACC2[k] = 0ull;      \
        _Pragma("unroll 1") for (int ii = 0; ii < DD; ii += 16) {              \
            const bool more = (ii + 16 < DD);                                  \
            if (more) {                                                        \
                _Pragma("unroll") for (int u = 0; u < 8; u++)                  \
                    wn[u] = Wcol[(ii + 16 + u) * DD];                          \
            }                                                                  \
            COMP8(wc, 0, ii, ACC2);                                            \
            if (more) {                                                        \
                _Pragma("unroll") for (int u = 0; u < 8; u++)                  \
                    wn[8 + u] = Wcol[(ii + 24 + u) * DD];                      \
            }                                                                  \
            COMP8(wc, 8, ii + 8, ACC2);                                        \
            _Pragma("unroll") for (int u = 0; u < 16; u++) wc[u] = wn[u];      \
        }                                                                      \
    } while (0)

#define ACCEL()                                                                \
    do {                                                                       \
        __syncthreads(); /* xt published */                                    \
        {                                                                      \
            unsigned long long acc2[S / 2];                                    \
            MATVEC(Wp1, xt_sm, acc2);                                          \
            _Pragma("unroll") for (int k = 0; k < S / 2; k++) {                \
                float2 p = unpack2(acc2[k]);                                   \
                float h0 = tanhf(p.x + bp);                                    \
                float h1 = tanhf(p.y + bp);                                    \
                float2 ssv;                                                    \
                ssv.x = (1.0f - h0 * h0) * w2;                                 \
                ssv.y = (1.0f - h1 * h1) * w2;                                 \
                *(float2*)(sv_sm + t * S + 2 * k) = ssv;                       \
            }                                                                  \
        }                                                                      \
        __syncthreads(); /* sv published */                                    \
        {                                                                      \
            unsigned long long acc2[S / 2];                                    \
            MATVEC(WpT, sv_sm, acc2);                                          \
            _Pragma("unroll") for (int k = 0; k < S / 2; k++) {                \
                float2 p = unpack2(acc2[k]);                                   \
                g[2 * k]     = p.x;                                            \
                g[2 * k + 1] = p.y;                                            \
            }                                                                  \
        }                                                                      \
        _Pragma("unroll") for (int s = 0; s < S; s++) {                        \
            float pg = g[s] * vt[s];                                           \
            float pv = vt[s] * vt[s];                                          \
            _Pragma("unroll") for (int off = 16; off > 0; off >>= 1) {         \
                pg += __shfl_xor_sync(0xffffffffu, pg, off);                   \
                pv += __shfl_xor_sync(0xffffffffu, pv, off);                   \
            }                                                                  \
            if (lane == 0) {                                                   \
                red_a[warp * S + s] = pg;                                      \
                red_b[warp * S + s] = pv;                                      \
            }                                                                  \
        }                                                                      \
        __syncthreads();                                                       \
        if (t < S) {                                                           \
            float sg = 0.f, sv2 = 0.f;                                         \
            _Pragma("unroll") for (int w8 = 0; w8 < 8; w8++) {                 \
                sg += red_a[w8 * S + t];                                       \
                sv2 += red_b[w8 * S + t];                                      \
            }                                                                  \
            bc_a[t] = sg;                                                      \
            bc_b[t] = sv2;                                                     \
        }                                                                      \
        __syncthreads();                                                       \
        _Pragma("unroll") for (int s = 0; s < S; s++) {                        \
            g[s] = 0.5f * bc_b[s] * g[s] - bc_a[s] * vt[s];                    \
        }                                                                      \
    } while (0)

    for (int step = 0; step < NSTEP; step++) {
        // ---- stage 1: a1 = acc(x, v)
#pragma unroll
        for (int s = 0; s < S; s++) {
            xt_sm[t * S + s] = x[s];
            vt[s] = v[s];
        }
        ACCEL();
#pragma unroll
        for (int s = 0; s < S; s++) {
            xa_sm[s * DD + t] = v[s];
            va_sm[s * DD + t] = g[s];
        }

        // ---- stage 2: a2 = acc(x + h/2 v, v + h/2 a1)
#pragma unroll
        for (int s = 0; s < S; s++) {
            xt_sm[t * S + s] = x[s] + 0.5f * hstep * v[s];
            vt[s] = v[s] + 0.5f * hstep * g[s];
        }
        ACCEL();
#pragma unroll
        for (int s = 0; s < S; s++) {
            xa_sm[s * DD + t] += 2.0f * vt[s];
            va_sm[s * DD + t] += 2.0f * g[s];
        }

        // ---- stage 3: a3 = acc(x + h/2 k2x, v + h/2 a2)   (k2x = current vt)
#pragma unroll
        for (int s = 0; s < S; s++) {
            float k2x = vt[s];
            xt_sm[t * S + s] = x[s] + 0.5f * hstep * k2x;
            vt[s] = v[s] + 0.5f * hstep * g[s];
        }
        ACCEL();
#pragma unroll
        for (int s = 0; s < S; s++) {
            xa_sm[s * DD + t] += 2.0f * vt[s];
            va_sm[s * DD + t] += 2.0f * g[s];
        }

        // ---- stage 4: a4 = acc(x + h k3x, v + h a3)   (k3x = current vt)
#pragma unroll
        for (int s = 0; s < S; s++) {
            float k3x = vt[s];
            xt_sm[t * S + s] = x[s] + hstep * k3x;
            vt[s] = v[s] + hstep * g[s];
        }
        ACCEL();
#pragma unroll
        for (int s = 0; s < S; s++) {
            float xacc = xa_sm[s * DD + t] + vt[s];
            float vacc = va_sm[s * DD + t] + g[s];
            x[s] += (hstep / 6.0f) * xacc;
            v[s] += (hstep / 6.0f) * vacc;
        }

        // ---- distance to z_e, track min
#pragma unroll
        for (int s = 0; s < S; s++) {
            float dd = x[s] - Z[(size_t)(NB + s0 + s) * DD + t];
            float p = dd * dd;
#pragma unroll
            for (int off = 16; off > 0; off >>= 1)
                p += __shfl_xor_sync(0xffffffffu, p, off);
            if (lane == 0) red_a[warp * S + s] = p;
        }
        __syncthreads();
        if (t < S) {
            float tot = 0.f;
#pragma unroll
            for (int w8 = 0; w8 < 8; w8++) tot += red_a[w8 * S + t];
            mymin = fminf(mymin, tot);
        }
        __syncthreads();
    }

    if (t < S) mind[s0 + t] = mymin;
#undef ACCEL
#undef MATVEC
#undef COMP8
}

// ---------------------------------------------------------------------------
// Deterministic final reduction: out = mean(mind) * WEIGHT
// ---------------------------------------------------------------------------
__global__ void reduce_kernel(const float* __restrict__ mind, float* __restrict__ out) {
    __shared__ float sm[1024];
    const int t = threadIdx.x;
    float a = mind[t] + mind[t + 1024] + mind[t + 2048] + mind[t + 3072];
    sm[t] = a;
    __syncthreads();
    for (int off = 512; off > 0; off >>= 1) {
        if (t < off) sm[t] += sm[t + off];
        __syncthreads();
    }
    if (t == 0) out[0] = sm[0] * (1.0f / (float)NB);
}

// ---------------------------------------------------------------------------
// Launch
// ---------------------------------------------------------------------------
extern "C" void kernel_launch(void* const* d_in, const int* in_sizes, int n_in,
                              void* d_out, int out_size) {
    const float* x_start = (const float*)d_in[0];
    const float* x_end   = (const float*)d_in[1];
    const float* noise   = (const float*)d_in[2];
    const float* W1  = (const float*)d_in[3];
    const float* b1  = (const float*)d_in[4];
    const float* W2  = (const float*)d_in[5];
    const float* b2  = (const float*)d_in[6];
    const float* Ww1 = (const float*)d_in[7];
    const float* bw1 = (const float*)d_in[8];
    const float* Ww2 = (const float*)d_in[9];
    const float* bw2 = (const float*)d_in[10];
    const float* Wp1 = (const float*)d_in[11];
    const float* bp1 = (const float*)d_in[12];
    const float* wp2 = (const float*)d_in[13];

    float *Hb, *Zb, *HWb, *Vb, *WpT, *Md;
    cudaGetSymbolAddress((void**)&Hb,  g_H);
    cudaGetSymbolAddress((void**)&Zb,  g_Z);
    cudaGetSymbolAddress((void**)&HWb, g_HW);
    cudaGetSymbolAddress((void**)&Vb,  g_V);
    cudaGetSymbolAddress((void**)&WpT, g_WpT);
    cudaGetSymbolAddress((void**)&Md,  g_mind);

    // allow >48KB dynamic smem for the trace kernel (idempotent host call)
    cudaFuncSetAttribute(trace_kernel,
                         cudaFuncAttributeMaxDynamicSharedMemorySize,
                         TR_SMEM_BYTES);

    // Wp1 transpose for the backward matvec
    transpose256<<<DD, DD>>>(Wp1, WpT);

    // Encoder layer 1 (start+end in ONE launch, 512 CTAs)
    sgemm_kernel<1><<<dim3(HH / 128, NB / 128, 2), 256>>>(
        x_start, x_end, W1, b1, Hb, NB, HH, DIN);
    // Encoder layer 2: Z = H @ W2 + b2  (both halves, BM=64 -> 256 CTAs)
    sgemm64_kernel<0><<<dim3(DD / 128, 2 * NB / 64), 256>>>(
        Hb, W2, b2, Zb, 2 * NB, DD, HH);
    // Wind field on z_s (BM=64 -> 128 CTAs each)
    sgemm64_kernel<1><<<dim3(DD / 128, NB / 64), 256>>>(
        Zb,  Ww1, bw1, HWb, NB, DD, DD);
    sgemm64_kernel<0><<<dim3(DD / 128, NB / 64), 256>>>(
        HWb, Ww2, bw2, Vb,  NB, DD, DD);
    // Degenerate-wind fallback
    fallback_kernel<<<NB, DD>>>(Vb, noise);
    // RK4 geodesic trace + per-sample min distance
    trace_kernel<<<NB / S, DD, TR_SMEM_BYTES>>>(Zb, Vb, Wp1, WpT, bp1, wp2, Md);
    // Mean
    reduce_kernel<<<1, 1024>>>(Md, (float*)d_out);
}

// round 8
// speedup vs baseline: 1.0296x; 1.0296x over previous
#include <cuda_runtime.h>
#include <cstdint>

// ---------------------------------------------------------------------------
// Problem constants
// ---------------------------------------------------------------------------
#define NB    4096      // batch
#define DIN   2048
#define HH    1024
#define DD    256       // latent dim == HW
#define NSTEP 15
#define S     16        // samples per trace CTA
#define TPB   128       // trace threads per block (2 dims per thread)

// ---------------------------------------------------------------------------
// Scratch (device globals; no allocation allowed)
// ---------------------------------------------------------------------------
__device__ float g_H   [2 * NB * HH];
__device__ float g_Z   [2 * NB * DD];   // z_s rows 0..4095, z_e rows 4096..8191
__device__ float g_HW  [NB * DD];
__device__ float g_V   [NB * DD];
__device__ float g_WpT [DD * DD];
__device__ float g_mind[NB];

// ---------------------------------------------------------------------------
// Packed fp32x2 helpers (FFMA2 — only reachable via PTX)
// ---------------------------------------------------------------------------
__device__ __forceinline__ unsigned long long pack2(float x, float y) {
    unsigned long long r;
    asm("mov.b64 %0, {%1, %2};" : "=l"(r) : "f"(x), "f"(y));
    return r;
}
__device__ __forceinline__ float2 unpack2(unsigned long long v) {
    float2 r;
    asm("mov.b64 {%0, %1}, %2;" : "=f"(r.x), "=f"(r.y) : "l"(v));
    return r;
}
__device__ __forceinline__ unsigned long long fma2(unsigned long long a,
                                                   unsigned long long b,
                                                   unsigned long long c) {
    unsigned long long d;
    asm("fma.rn.f32x2 %0, %1, %2, %3;" : "=l"(d) : "l"(a), "l"(b), "l"(c));
    return d;
}

// ---------------------------------------------------------------------------
// SGEMM (R4 exact): C[M,N] = act(A[M,K] @ B[K,N] + bias[N]), row-major.
// BM=BN=128, BK=16, 256 threads, 8x8 per thread, double-buffered smem.
// ---------------------------------------------------------------------------
#define ASTRIDE 132

template <int ACT>
__global__ __launch_bounds__(256)
void sgemm_kernel(const float* __restrict__ A, const float* __restrict__ Bm,
                  const float* __restrict__ bias, float* __restrict__ C,
                  int M, int N, int K) {
    __shared__ __align__(16) float As[2 * 16 * ASTRIDE];
    __shared__ __align__(16) float Bs[2 * 16 * 128];

    const int tid  = threadIdx.x;
    const int brow = blockIdx.y * 128;
    const int bcol = blockIdx.x * 128;
    const int ty   = tid >> 4;
    const int tx   = tid & 15;

    const int arow = tid >> 1;
    const int acol = (tid & 1) * 8;
    const int br0  = tid >> 5;
    const int bcl  = (tid & 31) * 4;

    const float* Aptr = A  + (size_t)(brow + arow) * K + acol;
    const float* Bptr = Bm + (size_t)br0 * N + bcol + bcl;

    unsigned long long c2[8][4];
#pragma unroll
    for (int m = 0; m < 8; m++)
#pragma unroll
        for (int j = 0; j < 4; j++) c2[m][j] = 0ull;

    float4 a_rg0, a_rg1, b_rg0, b_rg1;

    a_rg0 = *(const float4*)(Aptr + 0);
    a_rg1 = *(const float4*)(Aptr + 4);
    b_rg0 = *(const float4*)(Bptr);
    b_rg1 = *(const float4*)(Bptr + (size_t)8 * N);
    {
        float am[8] = {a_rg0.x, a_rg0.y, a_rg0.z, a_rg0.w,
                       a_rg1.x, a_rg1.y, a_rg1.z, a_rg1.w};
#pragma unroll
        for (int c = 0; c < 8; c++) As[(acol + c) * ASTRIDE + arow] = am[c];
        *(float4*)&Bs[br0 * 128 + bcl]       = b_rg0;
        *(float4*)&Bs[(br0 + 8) * 128 + bcl] = b_rg1;
    }
    __syncthreads();

    int buf = 0;
    const int nblk = K / 16;
    for (int kb = 0; kb < nblk; kb++) {
        const bool has_next = (kb + 1 < nblk);
        if (has_next) {
            const int k0 = (kb + 1) * 16;
            a_rg0 = *(const float4*)(Aptr + k0);
            a_rg1 = *(const float4*)(Aptr + k0 + 4);
            b_rg0 = *(const float4*)(Bptr + (size_t)k0 * N);
            b_rg1 = *(const float4*)(Bptr + (size_t)(k0 + 8) * N);
        }

        const float* Asb = As + buf * 16 * ASTRIDE;
        const float* Bsb = Bs + buf * 16 * 128;
#pragma unroll
        for (int kk = 0; kk < 16; kk++) {
            float4 a0 = *(const float4*)&Asb[kk * ASTRIDE + ty * 8];
            float4 a1 = *(const float4*)&Asb[kk * ASTRIDE + ty * 8 + 4];
            const unsigned long long* brow2 =
                (const unsigned long long*)&Bsb[kk * 128 + tx * 8];
            unsigned long long b2[4];
#pragma unroll
            for (int j = 0; j < 4; j++) b2[j] = brow2[j];
            float am[8] = {a0.x, a0.y, a0.z, a0.w, a1.x, a1.y, a1.z, a1.w};
#pragma unroll
            for (int m = 0; m < 8; m++) {
                unsigned long long aa = pack2(am[m], am[m]);
#pragma unroll
                for (int j = 0; j < 4; j++) c2[m][j] = fma2(aa, b2[j], c2[m][j]);
            }
        }

        if (has_next) {
            float* Asn = As + (buf ^ 1) * 16 * ASTRIDE;
            float* Bsn = Bs + (buf ^ 1) * 16 * 128;
            float am[8] = {a_rg0.x, a_rg0.y, a_rg0.z, a_rg0.w,
                           a_rg1.x, a_rg1.y, a_rg1.z, a_rg1.w};
#pragma unroll
            for (int c = 0; c < 8; c++) Asn[(acol + c) * ASTRIDE + arow] = am[c];
            *(float4*)&Bsn[br0 * 128 + bcl]       = b_rg0;
            *(float4*)&Bsn[(br0 + 8) * 128 + bcl] = b_rg1;
            __syncthreads();
            buf ^= 1;
        }
    }

#pragma unroll
    for (int m = 0; m < 8; m++) {
        const int row = brow + ty * 8 + m;
        float* crow = C + (size_t)row * N + bcol + tx * 8;
#pragma unroll
        for (int j = 0; j < 4; j++) {
            float2 p = unpack2(c2[m][j]);
            const int n = bcol + tx * 8 + 2 * j;
            p.x += bias[n];
            p.y += bias[n + 1];
            if (ACT) { p.x = tanhf(p.x); p.y = tanhf(p.y); }
            *(float2*)&crow[2 * j] = p;
        }
    }
}

// ---------------------------------------------------------------------------
// Wp1 transpose (tiny: 256x256)
// ---------------------------------------------------------------------------
__global__ void transpose256(const float* __restrict__ in, float* __restrict__ out) {
    int i = blockIdx.x, j = threadIdx.x;
    out[j * DD + i] = in[i * DD + j];
}

// ---------------------------------------------------------------------------
// Degenerate-wind fallback
// ---------------------------------------------------------------------------
__global__ void fallback_kernel(float* __restrict__ V, const float* __restrict__ noise) {
    __shared__ float rw[8], rn[8];
    const int s = blockIdx.x, t = threadIdx.x;
    const int lane = t & 31, warp = t >> 5;
    float w = V[s * DD + t];
    float n = noise[s * DD + t];
    float pw = w * w, pn = n * n;
#pragma unroll
    for (int off = 16; off > 0; off >>= 1) {
        pw += __shfl_xor_sync(0xffffffffu, pw, off);
        pn += __shfl_xor_sync(0xffffffffu, pn, off);
    }
    if (lane == 0) { rw[warp] = pw; rn[warp] = pn; }
    __syncthreads();
    float sw = 0.f, sn = 0.f;
#pragma unroll
    for (int i = 0; i < 8; i++) { sw += rw[i]; sn += rn[i]; }
    float wn = sqrtf(sw + 1e-24f);
    if (wn < 1e-5f) {
        float nn = sqrtf(sn + 1e-24f);
        V[s * DD + t] = w + n / (nn + 1e-12f) * 1e-4f;
    }
}

// ---------------------------------------------------------------------------
// Trace kernel v4: 128 threads, 2 output dims per thread (d0=t, d1=t+128),
// 16 samples per CTA. Halves smem-crossbar wavefronts per FMA vs v2.
// State/accumulators in thread-private smem columns [d*16+s], float4 access.
// Dynamic smem (floats):
//   xt[4096]|sv[4096]|xs[4096]|vs[4096]|xa[4096]|va[4096]
//   |red_a[64]|red_b[64]|bc_a[16]|bc_b[16]
// ---------------------------------------------------------------------------
#define TR_SMEM_FLOATS (6 * 4096 + 64 + 64 + 16 + 16)
#define TR_SMEM_BYTES  (TR_SMEM_FLOATS * 4)

__global__ __launch_bounds__(TPB)
void trace_kernel(const float* __restrict__ Z,    // [8192,256]: z_s | z_e
                  const float* __restrict__ V,    // [4096,256]
                  const float* __restrict__ Wp1,  // [256,256]
                  const float* __restrict__ WpT,  // transposed
                  const float* __restrict__ bp1,
                  const float* __restrict__ wp2,
                  float* __restrict__ mind) {
    extern __shared__ __align__(16) float dsm[];
    float* xt_sm = dsm;             // [d*16+s]
    float* sv_sm = dsm + 4096;      // [d*16+s]
    float* xs_sm = dsm + 8192;      // [d*16+s]
    float* vs_sm = dsm + 12288;     // [d*16+s]
    float* xa_sm = dsm + 16384;     // [d*16+s]
    float* va_sm = dsm + 20480;     // [d*16+s]
    float* red_a = dsm + 24576;     // [4*16]
    float* red_b = dsm + 24640;     // [4*16]
    float* bc_a  = dsm + 24704;     // [16]
    float* bc_b  = dsm + 24720;     // [16]

    const int t    = threadIdx.x;
    const int lane = t & 31;
    const int warp = t >> 5;        // 0..3
    const int d0   = t;
    const int d1   = t + 128;
    const int s0   = blockIdx.x * S;
    const float hstep = 1.0f / 15.0f;
    const float bpa = bp1[d0], bpb = bp1[d1];
    const float w2a = wp2[d0], w2b = wp2[d1];

    // load state (coalesced across threads at fixed s)
#pragma unroll
    for (int s = 0; s < S; s++) {
        xs_sm[d0 * S + s] = Z[(size_t)(s0 + s) * DD + d0];
        xs_sm[d1 * S + s] = Z[(size_t)(s0 + s) * DD + d1];
        vs_sm[d0 * S + s] = V[(size_t)(s0 + s) * DD + d0];
        vs_sm[d1 * S + s] = V[(size_t)(s0 + s) * DD + d1];
    }

    float vt0[S], vt1[S], g0[S], g1[S];
    float mymin = 3.4e38f;   // meaningful for t < 16

    // matvec for BOTH columns: acc{0,1}[k] (f32x2 pairs) over 256 rows,
    // 8-row blocks with one-block weight lookahead.
#define MATVEC2(WB, SRC)                                                       \
    do {                                                                       \
        const float* Wc0 = (WB) + d0;                                          \
        const float* Wc1 = (WB) + d1;                                          \
        const float* SRCP = (SRC);                                             \
        float wc0[8], wc1[8], wn0[8], wn1[8];                                  \
        _Pragma("unroll") for (int u = 0; u < 8; u++) {                        \
            wc0[u] = Wc0[u * DD];                                              \
            wc1[u] = Wc1[u * DD];                                              \
        }                                                                      \
        _Pragma("unroll") for (int k = 0; k < 8; k++) { acc0[k] = 0ull; acc1[k] = 0ull; } \
        _Pragma("unroll 1") for (int ii = 0; ii < DD; ii += 8) {               \
            if (ii + 8 < DD) {                                                 \
                _Pragma("unroll") for (int u = 0; u < 8; u++) {                \
                    wn0[u] = Wc0[(ii + 8 + u) * DD];                           \
                    wn1[u] = Wc1[(ii + 8 + u) * DD];                           \
                }                                                              \
            }                                                                  \
            _Pragma("unroll") for (int u = 0; u < 8; u++) {                    \
                unsigned long long w0 = pack2(wc0[u], wc0[u]);                 \
                unsigned long long w1 = pack2(wc1[u], wc1[u]);                 \
                const ulonglong2* xr = (const ulonglong2*)(SRCP + (ii + u) * S); \
                _Pragma("unroll") for (int k = 0; k < 4; k++) {                \
                    ulonglong2 xv = xr[k];                                     \
                    acc0[2 * k]     = fma2(w0, xv.x, acc0[2 * k]);             \
                    acc0[2 * k + 1] = fma2(w0, xv.y, acc0[2 * k + 1]);         \
                    acc1[2 * k]     = fma2(w1, xv.x, acc1[2 * k]);             \
                    acc1[2 * k + 1] = fma2(w1, xv.y, acc1[2 * k + 1]);         \
                }                                                              \
            }                                                                  \
            _Pragma("unroll") for (int u = 0; u < 8; u++) {                    \
                wc0[u] = wn0[u];                                               \
                wc1[u] = wn1[u];                                               \
            }                                                                  \
        }                                                                      \
    } while (0)

    // accel: xt_sm holds stage position; vt regs hold stage velocity.
    // result -> g0/g1 regs.
#define ACCEL()                                                                \
    do {                                                                       \
        __syncthreads(); /* xt published */                                    \
        unsigned long long acc0[8], acc1[8];                                   \
        MATVEC2(Wp1, xt_sm);                                                   \
        _Pragma("unroll") for (int k = 0; k < 8; k++) {                        \
            float2 p0 = unpack2(acc0[k]);                                      \
            float2 p1 = unpack2(acc1[k]);                                      \
            float ha = tanhf(p0.x + bpa), hb = tanhf(p0.y + bpa);              \
            float hc = tanhf(p1.x + bpb), hd = tanhf(p1.y + bpb);              \
            float2 sa, sb;                                                     \
            sa.x = (1.0f - ha * ha) * w2a;                                     \
            sa.y = (1.0f - hb * hb) * w2a;                                     \
            sb.x = (1.0f - hc * hc) * w2b;                                     \
            sb.y = (1.0f - hd * hd) * w2b;                                     \
            *(float2*)(sv_sm + d0 * S + 2 * k) = sa;                           \
            *(float2*)(sv_sm + d1 * S + 2 * k) = sb;                           \
        }                                                                      \
        __syncthreads(); /* sv published */                                    \
        MATVEC2(WpT, sv_sm);                                                   \
        _Pragma("unroll") for (int k = 0; k < 8; k++) {                        \
            float2 p0 = unpack2(acc0[k]);                                      \
            float2 p1 = unpack2(acc1[k]);                                      \
            g0[2 * k] = p0.x; g0[2 * k + 1] = p0.y;                            \
            g1[2 * k] = p1.x; g1[2 * k + 1] = p1.y;                            \
        }                                                                      \
        _Pragma("unroll") for (int s = 0; s < S; s++) {                        \
            float pg = g0[s] * vt0[s] + g1[s] * vt1[s];                        \
            float pv = vt0[s] * vt0[s] + vt1[s] * vt1[s];                      \
            _Pragma("unroll") for (int off = 16; off > 0; off >>= 1) {         \
                pg += __shfl_xor_sync(0xffffffffu, pg, off);                   \
                pv += __shfl_xor_sync(0xffffffffu, pv, off);                   \
            }                                                                  \
            if (lane == 0) {                                                   \
                red_a[warp * S + s] = pg;                                      \
                red_b[warp * S + s] = pv;                                      \
            }                                                                  \
        }                                                                      \
        __syncthreads();                                                       \
        if (t < S) {                                                           \
            float sg = 0.f, sv2 = 0.f;                                         \
            _Pragma("unroll") for (int w4 = 0; w4 < 4; w4++) {                 \
                sg  += red_a[w4 * S + t];                                      \
                sv2 += red_b[w4 * S + t];                                      \
            }                                                                  \
            bc_a[t] = sg;                                                      \
            bc_b[t] = sv2;                                                     \
        }                                                                      \
        __syncthreads();                                                       \
        _Pragma("unroll") for (int s = 0; s < S; s++) {                        \
            float ga = bc_a[s], vv = bc_b[s];                                  \
            g0[s] = 0.5f * vv * g0[s] - ga * vt0[s];                           \
            g1[s] = 0.5f * vv * g1[s] - ga * vt1[s];                           \
        }                                                                      \
    } while (0)

    for (int step = 0; step < NSTEP; step++) {
        // ---- stage 1: xt = x, vt = v
#pragma unroll
        for (int s = 0; s < S; s++) {
            float xv0 = xs_sm[d0 * S + s], xv1 = xs_sm[d1 * S + s];
            vt0[s] = vs_sm[d0 * S + s];
            vt1[s] = vs_sm[d1 * S + s];
            xt_sm[d0 * S + s] = xv0;
            xt_sm[d1 * S + s] = xv1;
        }
        ACCEL();
#pragma unroll
        for (int s = 0; s < S; s++) {
            xa_sm[d0 * S + s] = vt0[s];
            xa_sm[d1 * S + s] = vt1[s];
            va_sm[d0 * S + s] = g0[s];
            va_sm[d1 * S + s] = g1[s];
        }

        // ---- stage 2: xt = x + h/2 v, vt = v + h/2 a1
#pragma unroll
        for (int s = 0; s < S; s++) {
            float v0 = vs_sm[d0 * S + s], v1 = vs_sm[d1 * S + s];
            xt_sm[d0 * S + s] = xs_sm[d0 * S + s] + 0.5f * hstep * v0;
            xt_sm[d1 * S + s] = xs_sm[d1 * S + s] + 0.5f * hstep * v1;
            vt0[s] = v0 + 0.5f * hstep * g0[s];
            vt1[s] = v1 + 0.5f * hstep * g1[s];
        }
        ACCEL();
#pragma unroll
        for (int s = 0; s < S; s++) {
            xa_sm[d0 * S + s] += 2.0f * vt0[s];
            xa_sm[d1 * S + s] += 2.0f * vt1[s];
            va_sm[d0 * S + s] += 2.0f * g0[s];
            va_sm[d1 * S + s] += 2.0f * g1[s];
        }

        // ---- stage 3: xt = x + h/2 k2x (k2x = current vt), vt = v + h/2 a2
#pragma unroll
        for (int s = 0; s < S; s++) {
            xt_sm[d0 * S + s] = xs_sm[d0 * S + s] + 0.5f * hstep * vt0[s];
            xt_sm[d1 * S + s] = xs_sm[d1 * S + s] + 0.5f * hstep * vt1[s];
            float v0 = vs_sm[d0 * S + s], v1 = vs_sm[d1 * S + s];
            vt0[s] = v0 + 0.5f * hstep * g0[s];
            vt1[s] = v1 + 0.5f * hstep * g1[s];
        }
        ACCEL();
#pragma unroll
        for (int s = 0; s < S; s++) {
            xa_sm[d0 * S + s] += 2.0f * vt0[s];
            xa_sm[d1 * S + s] += 2.0f * vt1[s];
            va_sm[d0 * S + s] += 2.0f * g0[s];
            va_sm[d1 * S + s] += 2.0f * g1[s];
        }

        // ---- stage 4: xt = x + h k3x (k3x = current vt), vt = v + h a3
#pragma unroll
        for (int s = 0; s < S; s++) {
            xt_sm[d0 * S + s] = xs_sm[d0 * S + s] + hstep * vt0[s];
            xt_sm[d1 * S + s] = xs_sm[d1 * S + s] + hstep * vt1[s];
            float v0 = vs_sm[d0 * S + s], v1 = vs_sm[d1 * S + s];
            vt0[s] = v0 + hstep * g0[s];
            vt1[s] = v1 + hstep * g1[s];
        }
        ACCEL();

        // ---- final update + distance to z_e
        float xn0[S], xn1[S];
#pragma unroll
        for (int s = 0; s < S; s++) {
            float xacc0 = xa_sm[d0 * S + s] + vt0[s];
            float xacc1 = xa_sm[d1 * S + s] + vt1[s];
            float vacc0 = va_sm[d0 * S + s] + g0[s];
            float vacc1 = va_sm[d1 * S + s] + g1[s];
            xn0[s] = xs_sm[d0 * S + s] + (hstep / 6.0f) * xacc0;
            xn1[s] = xs_sm[d1 * S + s] + (hstep / 6.0f) * xacc1;
            xs_sm[d0 * S + s] = xn0[s];
            xs_sm[d1 * S + s] = xn1[s];
            vs_sm[d0 * S + s] += (hstep / 6.0f) * vacc0;
            vs_sm[d1 * S + s] += (hstep / 6.0f) * vacc1;
        }
#pragma unroll
        for (int s = 0; s < S; s++) {
            float ze0 = Z[(size_t)(NB + s0 + s) * DD + d0];
            float ze1 = Z[(size_t)(NB + s0 + s) * DD + d1];
            float dd0 = xn0[s] - ze0;
            float dd1 = xn1[s] - ze1;
            float p = dd0 * dd0 + dd1 * dd1;
#pragma unroll
            for (int off = 16; off > 0; off >>= 1)
                p += __shfl_xor_sync(0xffffffffu, p, off);
            if (lane == 0) red_a[warp * S + s] = p;
        }
        __syncthreads();
        if (t < S) {
            float tot = 0.f;
#pragma unroll
            for (int w4 = 0; w4 < 4; w4++) tot += red_a[w4 * S + t];
            mymin = fminf(mymin, tot);
        }
        __syncthreads();
    }

    if (t < S) mind[s0 + t] = mymin;
#undef ACCEL
#undef MATVEC2
}

// ---------------------------------------------------------------------------
// Deterministic final reduction: out = mean(mind) * WEIGHT
// ---------------------------------------------------------------------------
__global__ void reduce_kernel(const float* __restrict__ mind, float* __restrict__ out) {
    __shared__ float sm[1024];
    const int t = threadIdx.x;
    float a = mind[t] + mind[t + 1024] + mind[t + 2048] + mind[t + 3072];
    sm[t] = a;
    __syncthreads();
    for (int off = 512; off > 0; off >>= 1) {
        if (t < off) sm[t] += sm[t + off];
        __syncthreads();
    }
    if (t == 0) out[0] = sm[0] * (1.0f / (float)NB);
}

// ---------------------------------------------------------------------------
// Launch (GEMM config = R4 exact)
// ---------------------------------------------------------------------------
extern "C" void kernel_launch(void* const* d_in, const int* in_sizes, int n_in,
                              void* d_out, int out_size) {
    const float* x_start = (const float*)d_in[0];
    const float* x_end   = (const float*)d_in[1];
    const float* noise   = (const float*)d_in[2];
    const float* W1  = (const float*)d_in[3];
    const float* b1  = (const float*)d_in[4];
    const float* W2  = (const float*)d_in[5];
    const float* b2  = (const float*)d_in[6];
    const float* Ww1 = (const float*)d_in[7];
    const float* bw1 = (const float*)d_in[8];
    const float* Ww2 = (const float*)d_in[9];
    const float* bw2 = (const float*)d_in[10];
    const float* Wp1 = (const float*)d_in[11];
    const float* bp1 = (const float*)d_in[12];
    const float* wp2 = (const float*)d_in[13];

    float *Hb, *Zb, *HWb, *Vb, *WpT, *Md;
    cudaGetSymbolAddress((void**)&Hb,  g_H);
    cudaGetSymbolAddress((void**)&Zb,  g_Z);
    cudaGetSymbolAddress((void**)&HWb, g_HW);
    cudaGetSymbolAddress((void**)&Vb,  g_V);
    cudaGetSymbolAddress((void**)&WpT, g_WpT);
    cudaGetSymbolAddress((void**)&Md,  g_mind);

    // allow >48KB dynamic smem for the trace kernel (idempotent host call)
    cudaFuncSetAttribute(trace_kernel,
                         cudaFuncAttributeMaxDynamicSharedMemorySize,
                         TR_SMEM_BYTES);

    // Wp1 transpose for the backward matvec
    transpose256<<<DD, DD>>>(Wp1, WpT);

    // Encoder layer 1: H = tanh(X @ W1 + b1)   (start, end)
    sgemm_kernel<1><<<dim3(HH / 128, NB / 128), 256>>>(x_start, W1, b1, Hb, NB, HH, DIN);
    sgemm_kernel<1><<<dim3(HH / 128, NB / 128), 256>>>(x_end,   W1, b1, Hb + (size_t)NB * HH, NB, HH, DIN);
    // Encoder layer 2: Z = H @ W2 + b2   (both halves at once)
    sgemm_kernel<0><<<dim3(DD / 128, 2 * NB / 128), 256>>>(Hb, W2, b2, Zb, 2 * NB, DD, HH);
    // Wind field on z_s
    sgemm_kernel<1><<<dim3(DD / 128, NB / 128), 256>>>(Zb,  Ww1, bw1, HWb, NB, DD, DD);
    sgemm_kernel<0><<<dim3(DD / 128, NB / 128), 256>>>(HWb, Ww2, bw2, Vb,  NB, DD, DD);
    // Degenerate-wind fallback
    fallback_kernel<<<NB, DD>>>(Vb, noise);
    // RK4 geodesic trace + per-sample min distance
    trace_kernel<<<NB / S, TPB, TR_SMEM_BYTES>>>(Zb, Vb, Wp1, WpT, bp1, wp2, Md);
    // Mean
    reduce_kernel<<<1, 1024>>>(Md, (float*)d_out);
}